// round 9
// baseline (speedup 1.0000x reference)
#include <cuda_runtime.h>
#include <math.h>

#define Bn 8
#define Tn 2048
#define Dn 64
#define Fn 128
#define NCH 64      // T-chunks in k3 / partial
#define TC 32       // T per k3 chunk
#define T1 32       // T per k1 CTA

// ---------------- scratch (static device globals: allocation-free) ----------------
__device__ float g_w[(size_t)Bn * Tn * Dn];             // [b][t][d], 4 MB
__device__ float g_psum[Bn * NCH * Dn];                 // per-chunk sum_t w
__device__ float g_partial[(size_t)Bn * NCH * Dn * Fn]; // [b][ch][d][f], 16 MB

typedef unsigned long long u64;
#define PACK2(dst, lo, hi)   asm("mov.b64 %0, {%1, %2};" : "=l"(dst) : "f"(lo), "f"(hi))
#define UNPACK2(lo, hi, src) asm("mov.b64 {%0, %1}, %2;" : "=f"(lo), "=f"(hi) : "l"(src))
#define FFMA2(d_, a_, b_, c_) asm("fma.rn.f32x2 %0, %1, %2, %3;" : "=l"(d_) : "l"(a_), "l"(b_), "l"(c_))

// ======== k1: w[b][t][d] = exp(+sqrt(||x_t - dic_d||^2) * a[d]) ========
// grid (64, 8) = 512 CTAs x 128 thr, micro-tile 4t x 4d.
// Inner loop: 3 LDS.128 + 10 FFMA2, ZERO packs (operands pre-paired/dup'd in smem).
struct __align__(16) Smem1 {
    float sxT[Fn][36];       // [k][t], col rotated by 4*((k>>2)&7)      18.4 KB
    float sdD[64][128];      // [k-chunk][2d] pre-DUPLICATED dic          32 KB
    float sa[Dn];
    float sdd[Dn];
};
__global__ void __launch_bounds__(128) k1(const float* __restrict__ x,
                                          const float* __restrict__ dic,
                                          const float* __restrict__ wei) {
    extern __shared__ __align__(16) char smem_raw[];
    Smem1& sm = *(Smem1*)smem_raw;
    int b = blockIdx.y;
    int t_base = blockIdx.x * T1;
    int tid = threadIdx.x;
    int dgrp = tid & 15, tgrp = tid >> 4;   // 16 x 8
    int d0 = dgrp * 4, t0 = tgrp * 4;

    if (tid < 32) {           // a[d] = lse(wei) - wei[d]
        float w0 = wei[tid], w1 = wei[tid + 32];
        float mx = fmaxf(w0, w1);
        #pragma unroll
        for (int o = 16; o; o >>= 1) mx = fmaxf(mx, __shfl_xor_sync(0xffffffffu, mx, o));
        float s = __expf(w0 - mx) + __expf(w1 - mx);
        #pragma unroll
        for (int o = 16; o; o >>= 1) s += __shfl_xor_sync(0xffffffffu, s, o);
        float lse = mx + logf(s);
        sm.sa[tid]      = lse - w0;
        sm.sa[tid + 32] = lse - w1;
    }
    if (tid < Dn) {           // ||dic_d||^2 (dic is L2-hot across 512 CTAs)
        float dd = 0.f;
        const float4* dp = (const float4*)(dic + (size_t)tid * Fn);
        #pragma unroll 8
        for (int q = 0; q < Fn / 4; q++) {
            float4 v = dp[q];
            dd += v.x * v.x + v.y * v.y + v.z * v.z + v.w * v.w;
        }
        sm.sdd[tid] = dd;
    }
    // stage x transposed: read x[t][4*f4..], write rows k=4*f4+i at rotated col
    #pragma unroll
    for (int q = 0; q < 8; q++) {
        int qi = q * 128 + tid;
        int t = qi >> 5;                 // 0..31
        int f4 = qi & 31;                // 0..31
        float4 v = *(const float4*)(x + (size_t)(b * Tn + t_base + t) * Fn + 4 * f4);
        int col = (t + ((f4 & 7) << 2)) & 31;    // rotation: 4-way (not 16) STS conflicts
        sm.sxT[4 * f4 + 0][col] = v.x;
        sm.sxT[4 * f4 + 1][col] = v.y;
        sm.sxT[4 * f4 + 2][col] = v.z;
        sm.sxT[4 * f4 + 3][col] = v.w;
    }

    u64 acc[4][2];            // [d j][t-pair p]
    u64 xx0 = 0, xx1 = 0;
    #pragma unroll
    for (int j = 0; j < 4; j++) acc[j][0] = acc[j][1] = 0ULL;

    int dread = tid >> 1;                // dic row for staging
    int fo = (tid & 1) * 32;

    #pragma unroll 1
    for (int kc = 0; kc < 2; kc++) {
        if (kc) __syncthreads();         // protect sdD reuse
        // stage dup'd dic chunk: 64 k x 64 d -> sdD[k][2d] (values duplicated)
        #pragma unroll
        for (int q = 0; q < 8; q++) {
            int f = fo + 4 * q;          // local k base
            float4 v = *(const float4*)(dic + (size_t)dread * Fn + kc * 64 + f);
            u64 p0, p1, p2, p3;
            PACK2(p0, v.x, v.x); PACK2(p1, v.y, v.y);
            PACK2(p2, v.z, v.z); PACK2(p3, v.w, v.w);
            *(u64*)&sm.sdD[f + 0][2 * dread] = p0;
            *(u64*)&sm.sdD[f + 1][2 * dread] = p1;
            *(u64*)&sm.sdD[f + 2][2 * dread] = p2;
            *(u64*)&sm.sdD[f + 3][2 * dread] = p3;
        }
        __syncthreads();

        #pragma unroll 4
        for (int kq = 0; kq < 16; kq++) {
            int rot = ((kc * 16 + kq) & 7) << 2;
            int cx = (t0 + rot) & 31;
            #pragma unroll
            for (int kk = 0; kk < 4; kk++) {
                int kl = kq * 4 + kk;
                ulonglong2 tp = *(ulonglong2*)&sm.sxT[kc * 64 + kl][cx]; // (t0,t1),(t2,t3)
                ulonglong2 da = *(ulonglong2*)&sm.sdD[kl][2 * d0];       // (d0,d0),(d1,d1)
                ulonglong2 db = *(ulonglong2*)&sm.sdD[kl][2 * d0 + 4];   // (d2,d2),(d3,d3)
                FFMA2(xx0, tp.x, tp.x, xx0);
                FFMA2(xx1, tp.y, tp.y, xx1);
                FFMA2(acc[0][0], tp.x, da.x, acc[0][0]);
                FFMA2(acc[0][1], tp.y, da.x, acc[0][1]);
                FFMA2(acc[1][0], tp.x, da.y, acc[1][0]);
                FFMA2(acc[1][1], tp.y, da.y, acc[1][1]);
                FFMA2(acc[2][0], tp.x, db.x, acc[2][0]);
                FFMA2(acc[2][1], tp.y, db.x, acc[2][1]);
                FFMA2(acc[3][0], tp.x, db.y, acc[3][0]);
                FFMA2(acc[3][1], tp.y, db.y, acc[3][1]);
            }
        }
    }

    float xxv[4];
    UNPACK2(xxv[0], xxv[1], xx0);
    UNPACK2(xxv[2], xxv[3], xx1);
    float dot[4][4];          // [t i][d j]
    #pragma unroll
    for (int j = 0; j < 4; j++) {
        UNPACK2(dot[0][j], dot[1][j], acc[j][0]);
        UNPACK2(dot[2][j], dot[3][j], acc[j][1]);
    }
    float4 dd4 = *(float4*)&sm.sdd[d0];
    float4 a4  = *(float4*)&sm.sa[d0];
    float ddv[4] = {dd4.x, dd4.y, dd4.z, dd4.w};
    float av[4]  = {a4.x, a4.y, a4.z, a4.w};
    #pragma unroll
    for (int i = 0; i < 4; i++) {
        float o[4];
        #pragma unroll
        for (int j = 0; j < 4; j++) {
            float d2 = fmaxf(xxv[i] + ddv[j] - 2.0f * dot[i][j], 0.0f);
            // logit = +dis*a in ~[42,71]; exp finite fp32 -> no max-subtraction pass
            o[j] = __expf(sqrtf(d2) * av[j]);
        }
        *(float4*)(g_w + (size_t)(b * Tn + t_base + t0 + i) * Dn + d0) =
            make_float4(o[0], o[1], o[2], o[3]);
    }
}

// ======== k3: partial[b][ch][d][f] = sum_t w*x ; psum = sum_t w ========
// grid (64, 8) = 512 CTAs x 256 thr, micro-tile 4d x 8f, TC=32.
// Inner loop: 4 LDS.128 + 16 FFMA2, zero packs (w pre-duplicated in smem).
struct __align__(16) Smem3 {
    float sx[TC][Fn];        // natural [t][f]                            16 KB
    float swD[TC][Fn];       // [t][2d] pre-DUP w, parity-rotated cols    16 KB
};
__global__ void __launch_bounds__(256) k3(const float* __restrict__ x) {
    extern __shared__ __align__(16) char smem_raw[];
    Smem3& sm = *(Smem3*)smem_raw;
    int ch = blockIdx.x, b = blockIdx.y;
    int tid = threadIdx.x;
    int dgrp = tid & 15, fgrp = tid >> 4;
    int d0 = dgrp * 4, f0 = fgrp * 8;
    int dg8 = dgrp * 8;
    int t_base = ch * TC;

    // stage x (32t x 128f) coalesced
    #pragma unroll
    for (int q = 0; q < 4; q++) {
        int qi = q * 256 + tid;
        int r = qi >> 5, c = (qi & 31) * 4;
        *(float4*)&sm.sx[r][c] =
            *(const float4*)(x + (size_t)(b * Tn + t_base + r) * Fn + c);
    }
    // stage w duplicated: read g_w[t][4*d4..], write pairs at parity-rotated col
    #pragma unroll
    for (int q = 0; q < 2; q++) {
        int qi = q * 256 + tid;
        int t = qi >> 4, d4 = qi & 15;
        float4 v = *(const float4*)(g_w + (size_t)(b * Tn + t_base + t) * Dn + 4 * d4);
        int cb = (8 * d4 + ((t & 1) << 4)) & 127;
        u64 p0, p1, p2, p3;
        PACK2(p0, v.x, v.x); PACK2(p1, v.y, v.y);
        PACK2(p2, v.z, v.z); PACK2(p3, v.w, v.w);
        *(u64*)&sm.swD[t][cb + 0] = p0;
        *(u64*)&sm.swD[t][cb + 2] = p1;
        *(u64*)&sm.swD[t][cb + 4] = p2;
        *(u64*)&sm.swD[t][cb + 6] = p3;
    }
    __syncthreads();

    u64 a2[4][4];             // [d][f-pair]
    #pragma unroll
    for (int i = 0; i < 4; i++)
        #pragma unroll
        for (int fp = 0; fp < 4; fp++) a2[i][fp] = 0ULL;

    #pragma unroll 8
    for (int t = 0; t < TC; t++) {
        int cw = (dg8 + ((t & 1) << 4)) & 127;
        ulonglong2 pa = *(ulonglong2*)&sm.swD[t][cw];      // (d0,d0),(d1,d1)
        ulonglong2 pb = *(ulonglong2*)&sm.swD[t][cw + 4];  // (d2,d2),(d3,d3)
        ulonglong2 fa = *(ulonglong2*)&sm.sx[t][f0];       // free f-pairs
        ulonglong2 fb = *(ulonglong2*)&sm.sx[t][f0 + 4];
        FFMA2(a2[0][0], pa.x, fa.x, a2[0][0]); FFMA2(a2[0][1], pa.x, fa.y, a2[0][1]);
        FFMA2(a2[0][2], pa.x, fb.x, a2[0][2]); FFMA2(a2[0][3], pa.x, fb.y, a2[0][3]);
        FFMA2(a2[1][0], pa.y, fa.x, a2[1][0]); FFMA2(a2[1][1], pa.y, fa.y, a2[1][1]);
        FFMA2(a2[1][2], pa.y, fb.x, a2[1][2]); FFMA2(a2[1][3], pa.y, fb.y, a2[1][3]);
        FFMA2(a2[2][0], pb.x, fa.x, a2[2][0]); FFMA2(a2[2][1], pb.x, fa.y, a2[2][1]);
        FFMA2(a2[2][2], pb.x, fb.x, a2[2][2]); FFMA2(a2[2][3], pb.x, fb.y, a2[2][3]);
        FFMA2(a2[3][0], pb.y, fa.x, a2[3][0]); FFMA2(a2[3][1], pb.y, fa.y, a2[3][1]);
        FFMA2(a2[3][2], pb.y, fb.x, a2[3][2]); FFMA2(a2[3][3], pb.y, fb.y, a2[3][3]);
    }

    // per-chunk weight sums from the dup tile (read one half of each pair)
    if (tid < Dn) {
        int cg = (tid >> 2) * 8, cj = (tid & 3) * 2;
        float s = 0.f;
        #pragma unroll 8
        for (int t = 0; t < TC; t++)
            s += sm.swD[t][((cg + ((t & 1) << 4)) & 127) + cj];
        g_psum[(b * NCH + ch) * Dn + tid] = s;
    }

    float* pp = g_partial + ((size_t)(b * NCH + ch) * Dn) * Fn;
    #pragma unroll
    for (int i = 0; i < 4; i++) {
        float o[8];
        #pragma unroll
        for (int fp = 0; fp < 4; fp++) UNPACK2(o[2 * fp], o[2 * fp + 1], a2[i][fp]);
        float* row = pp + (size_t)(d0 + i) * Fn + f0;
        *(float4*)(row)     = make_float4(o[0], o[1], o[2], o[3]);
        *(float4*)(row + 4) = make_float4(o[4], o[5], o[6], o[7]);
    }
}

// ======== k4: out[b][d][f] = (sum_ch partial)/P - dic ========
// grid 512 = one block per (b,d), 256 thr: 8 groups x 8 unrolled chunks (MLP 8).
__global__ void __launch_bounds__(256) k4(const float* __restrict__ dic,
                                          float* __restrict__ out) {
    __shared__ float4 sp[8][32];
    __shared__ float sP;
    int bd = blockIdx.x;
    int b = bd >> 6, d = bd & 63;
    int tid = threadIdx.x;
    int f4 = tid & 31, grp = tid >> 5;

    if (tid < 32) {           // P = sum_ch psum (64 chunks)
        float s = g_psum[(b * NCH + tid) * Dn + d]
                + g_psum[(b * NCH + tid + 32) * Dn + d];
        #pragma unroll
        for (int o = 16; o; o >>= 1) s += __shfl_xor_sync(0xffffffffu, s, o);
        if (tid == 0) sP = s;
    }

    const float4* p = (const float4*)g_partial
        + ((size_t)(b * NCH + grp * 8) * Dn + d) * (Fn / 4) + f4;
    float4 s = make_float4(0.f, 0.f, 0.f, 0.f);
    #pragma unroll
    for (int i = 0; i < 8; i++) {
        float4 v = p[(size_t)i * Dn * (Fn / 4)];
        s.x += v.x; s.y += v.y; s.z += v.z; s.w += v.w;
    }
    sp[grp][f4] = s;
    __syncthreads();

    if (tid < 32) {
        float4 r = make_float4(0.f, 0.f, 0.f, 0.f);
        #pragma unroll
        for (int g = 0; g < 8; g++) {
            float4 v = sp[g][f4];
            r.x += v.x; r.y += v.y; r.z += v.z; r.w += v.w;
        }
        float inv = 1.0f / sP;
        float4 dc = ((const float4*)dic)[d * (Fn / 4) + f4];
        ((float4*)out)[bd * (Fn / 4) + f4] =
            make_float4(r.x * inv - dc.x, r.y * inv - dc.y,
                        r.z * inv - dc.z, r.w * inv - dc.w);
    }
}

// ---------------- launch ----------------
extern "C" void kernel_launch(void* const* d_in, const int* in_sizes, int n_in,
                              void* d_out, int out_size) {
    const float* x = 0; const float* dic = 0; const float* wei = 0;
    for (int i = 0; i < n_in; i++) {
        if (in_sizes[i] == Bn * Tn * Fn)      x   = (const float*)d_in[i];
        else if (in_sizes[i] == Dn * Fn)      dic = (const float*)d_in[i];
        else if (in_sizes[i] == Dn)           wei = (const float*)d_in[i];
    }
    float* out = (float*)d_out;

    int s1 = (int)sizeof(Smem1);   // ~51.7 KB
    int s3 = (int)sizeof(Smem3);   // 32 KB
    cudaFuncSetAttribute(k1, cudaFuncAttributeMaxDynamicSharedMemorySize, s1);
    cudaFuncSetAttribute(k3, cudaFuncAttributeMaxDynamicSharedMemorySize, s3);

    k1<<<dim3(Tn / T1, Bn), 128, s1>>>(x, dic, wei);
    k3<<<dim3(NCH, Bn), 256, s3>>>(x);
    k4<<<Bn * Dn, 256>>>(dic, out);
}

// round 12
// speedup vs baseline: 1.3954x; 1.3954x over previous
#include <cuda_runtime.h>
#include <math.h>

#define Bn 8
#define Tn 2048
#define Dn 64
#define Fn 128
#define NCH 32      // T-chunks in k3 / partial
#define TC 64       // T per k3 chunk
#define T1 32       // T per k1 CTA

// ---------------- scratch (static device globals: allocation-free) ----------------
__device__ float g_w[(size_t)Bn * Tn * Dn];             // [b][t][d], 4 MB
__device__ float g_psum[Bn * NCH * Dn];                 // per-chunk sum_t w
__device__ float g_partial[(size_t)Bn * NCH * Dn * Fn]; // [b][ch][d][f], 8 MB

typedef unsigned long long u64;
#define PACK2(dst, lo, hi)   asm("mov.b64 %0, {%1, %2};" : "=l"(dst) : "f"(lo), "f"(hi))
#define UNPACK2(lo, hi, src) asm("mov.b64 {%0, %1}, %2;" : "=f"(lo), "=f"(hi) : "l"(src))
#define FFMA2(d_, a_, b_, c_) asm("fma.rn.f32x2 %0, %1, %2, %3;" : "=l"(d_) : "l"(a_), "l"(b_), "l"(c_))

// ======== k1: w[b][t][d] = exp(+sqrt(||x_t - dic_d||^2) * a[d]) ========
// grid (64, 8) = 512 CTAs x 128 thr, micro-tile 4t x 4d.
// Inner loop: 3 LDS.128 + 8 FFMA2, zero packs.
//   x DUP'd in smem (2 broadcast addrs/warp -> conflict-free),
//   dic natural transposed (16x16B consecutive -> conflict-free pairs).
struct __align__(16) Smem1 {
    float sxD[128][64];   // [k][2t] dup'd x pairs, 32 KB
    float sdT[64][64];    // [k-local][d] transposed dic chunk, 16 KB
    float sa[Dn];         // lse(wei) - wei[d]
    float sdd[Dn];        // ||dic_d||^2
    float sxxp[4][32];    // per-warp ||x_t||^2 partials
};
__global__ void __launch_bounds__(128) k1(const float* __restrict__ x,
                                          const float* __restrict__ dic,
                                          const float* __restrict__ wei) {
    extern __shared__ __align__(16) char smem_raw[];
    Smem1& sm = *(Smem1*)smem_raw;
    int b = blockIdx.y;
    int t_base = blockIdx.x * T1;
    int tid = threadIdx.x;
    int lane = tid & 31, w = tid >> 5;

    if (tid < 32) {           // a[d] = lse(wei) - wei[d]
        float w0 = wei[tid], w1 = wei[tid + 32];
        float mx = fmaxf(w0, w1);
        #pragma unroll
        for (int o = 16; o; o >>= 1) mx = fmaxf(mx, __shfl_xor_sync(0xffffffffu, mx, o));
        float s = __expf(w0 - mx) + __expf(w1 - mx);
        #pragma unroll
        for (int o = 16; o; o >>= 1) s += __shfl_xor_sync(0xffffffffu, s, o);
        float lse = mx + logf(s);
        sm.sa[tid]      = lse - w0;
        sm.sa[tid + 32] = lse - w1;
    }
    if (tid < Dn) {           // ||dic_d||^2 (dic L2-hot across 512 CTAs)
        float dd = 0.f;
        const float4* dp = (const float4*)(dic + (size_t)tid * Fn);
        #pragma unroll 8
        for (int q = 0; q < Fn / 4; q++) {
            float4 v = dp[q];
            dd += v.x * v.x + v.y * v.y + v.z * v.z + v.w * v.w;
        }
        sm.sdd[tid] = dd;
    }
    // stage x dup'd: lane = t, warp w covers k in [32w, 32w+32).
    // STS.64: fixed row k, lanes = cols -> 256B consecutive, conflict-free.
    {
        const float* xr = x + (size_t)(b * Tn + t_base + lane) * Fn + w * 32;
        float pxx = 0.f;
        #pragma unroll
        for (int q = 0; q < 8; q++) {
            float4 v = *(const float4*)(xr + 4 * q);
            pxx = fmaf(v.x, v.x, fmaf(v.y, v.y, fmaf(v.z, v.z, fmaf(v.w, v.w, pxx))));
            int k = w * 32 + 4 * q;
            u64 p0, p1, p2, p3;
            PACK2(p0, v.x, v.x); PACK2(p1, v.y, v.y);
            PACK2(p2, v.z, v.z); PACK2(p3, v.w, v.w);
            *(u64*)&sm.sxD[k + 0][2 * lane] = p0;
            *(u64*)&sm.sxD[k + 1][2 * lane] = p1;
            *(u64*)&sm.sxD[k + 2][2 * lane] = p2;
            *(u64*)&sm.sxD[k + 3][2 * lane] = p3;
        }
        sm.sxxp[w][lane] = pxx;   // ||x_t||^2 partial over this warp's 32 k
    }

    int dgrp = tid & 15, tgrp = tid >> 4;   // 16 d-groups x 8 t-groups
    int d0 = dgrp * 4, t0 = tgrp * 4;
    u64 acc[4][2];            // [t][d-pair]
    #pragma unroll
    for (int i = 0; i < 4; i++) acc[i][0] = acc[i][1] = 0ULL;

    int dr_ = tid & 63, h = tid >> 6;       // dic staging role
    #pragma unroll 1
    for (int kc = 0; kc < 2; kc++) {
        __syncthreads();      // (kc=0: orders sxD/sa/sdd/sxxp; kc=1: protects sdT reuse)
        // stage dic chunk transposed: thread (dr_, h) covers k in [32h, 32h+32) of col dr_
        const float* dp = dic + (size_t)dr_ * Fn + kc * 64 + h * 32;
        #pragma unroll
        for (int q = 0; q < 8; q++) {
            float4 v = *(const float4*)(dp + 4 * q);
            int kl = h * 32 + 4 * q;
            sm.sdT[kl + 0][dr_] = v.x;    // lanes = consecutive d: conflict-free
            sm.sdT[kl + 1][dr_] = v.y;
            sm.sdT[kl + 2][dr_] = v.z;
            sm.sdT[kl + 3][dr_] = v.w;
        }
        __syncthreads();

        const float (*sxDk)[64] = &sm.sxD[kc * 64];
        #pragma unroll 4
        for (int kl = 0; kl < 64; kl++) {
            ulonglong2 xa = *(const ulonglong2*)&sxDk[kl][2 * t0];      // dup(t0),dup(t1)
            ulonglong2 xb = *(const ulonglong2*)&sxDk[kl][2 * t0 + 4];  // dup(t2),dup(t3)
            ulonglong2 da = *(const ulonglong2*)&sm.sdT[kl][d0];        // (d0,d1),(d2,d3)
            FFMA2(acc[0][0], xa.x, da.x, acc[0][0]);
            FFMA2(acc[0][1], xa.x, da.y, acc[0][1]);
            FFMA2(acc[1][0], xa.y, da.x, acc[1][0]);
            FFMA2(acc[1][1], xa.y, da.y, acc[1][1]);
            FFMA2(acc[2][0], xb.x, da.x, acc[2][0]);
            FFMA2(acc[2][1], xb.x, da.y, acc[2][1]);
            FFMA2(acc[3][0], xb.y, da.x, acc[3][0]);
            FFMA2(acc[3][1], xb.y, da.y, acc[3][1]);
        }
    }

    float4 dd4 = *(float4*)&sm.sdd[d0];
    float4 a4  = *(float4*)&sm.sa[d0];
    float ddv[4] = {dd4.x, dd4.y, dd4.z, dd4.w};
    float av[4]  = {a4.x, a4.y, a4.z, a4.w};
    #pragma unroll
    for (int i = 0; i < 4; i++) {           // t row
        float xxv = sm.sxxp[0][t0 + i] + sm.sxxp[1][t0 + i]
                  + sm.sxxp[2][t0 + i] + sm.sxxp[3][t0 + i];
        float dot[4];
        UNPACK2(dot[0], dot[1], acc[i][0]);
        UNPACK2(dot[2], dot[3], acc[i][1]);
        float o[4];
        #pragma unroll
        for (int j = 0; j < 4; j++) {
            float d2 = fmaxf(xxv + ddv[j] - 2.0f * dot[j], 0.0f);
            // logit = +dis*a in ~[42,71]; exp finite fp32 -> no max-subtraction pass
            o[j] = __expf(sqrtf(d2) * av[j]);
        }
        *(float4*)(g_w + (size_t)(b * Tn + t_base + t0 + i) * Dn + d0) =
            make_float4(o[0], o[1], o[2], o[3]);
    }
}

// ======== k3: partial[b][ch][d][f] = sum_t w*x ; psum = sum_t w ========
// grid (32, 8) = 256 CTAs x 256 thr, micro-tile 4d x 8f, TC=64.
// Inner loop: 5 LDS.128 + 16 FFMA2, zero packs.
//   w natural (free d-pairs, 16x16B conflict-free), x DUP'd (2 addrs/warp).
struct __align__(16) Smem3 {
    float sxD[TC][2 * Fn];   // [t][2f] dup'd x, 64 KB
    float sw[TC][Dn + 4];    // [t][d] natural w, pad 68, ~17.4 KB
};
__global__ void __launch_bounds__(256) k3(const float* __restrict__ x) {
    extern __shared__ __align__(16) char smem_raw[];
    Smem3& sm = *(Smem3*)smem_raw;
    int ch = blockIdx.x, b = blockIdx.y;
    int tid = threadIdx.x;
    int dgrp = tid & 15, fgrp = tid >> 4;   // 16 x 16
    int d0 = dgrp * 4, f0 = fgrp * 8;
    int t_base = ch * TC;

    // stage w natural (coalesced): 64t x 64d = 1024 float4 = 4 per thread
    #pragma unroll
    for (int q = 0; q < 4; q++) {            // FIX (R9 bug): was q < 2 -> half tile
        int qi = q * 256 + tid;
        int t = qi >> 4, d4 = (qi & 15) * 4;
        *(float4*)&sm.sw[t][d4] =
            *(const float4*)(g_w + (size_t)(b * Tn + t_base + t) * Dn + d4);
    }
    // stage x dup'd: lane-major f -> STS.64 256B consecutive per warp, conflict-free
    {
        int f = tid & 127, th = tid >> 7;
        const float* xc = x + (size_t)(b * Tn + t_base + th) * Fn + f;
        #pragma unroll
        for (int q = 0; q < 32; q++) {
            float v = xc[(size_t)(2 * q) * Fn];
            u64 p; PACK2(p, v, v);
            *(u64*)&sm.sxD[2 * q + th][2 * f] = p;
        }
    }
    __syncthreads();

    u64 acc[2][8];            // [d-pair][f]
    #pragma unroll
    for (int j = 0; j < 2; j++)
        #pragma unroll
        for (int f = 0; f < 8; f++) acc[j][f] = 0ULL;

    #pragma unroll 4
    for (int t = 0; t < TC; t++) {
        ulonglong2 wp = *(const ulonglong2*)&sm.sw[t][d0];          // (d0,d1),(d2,d3)
        ulonglong2 x0 = *(const ulonglong2*)&sm.sxD[t][2 * f0];     // dup f0, f1
        ulonglong2 x1 = *(const ulonglong2*)&sm.sxD[t][2 * f0 + 4]; // dup f2, f3
        ulonglong2 x2 = *(const ulonglong2*)&sm.sxD[t][2 * f0 + 8]; // dup f4, f5
        ulonglong2 x3 = *(const ulonglong2*)&sm.sxD[t][2 * f0 + 12];// dup f6, f7
        FFMA2(acc[0][0], wp.x, x0.x, acc[0][0]); FFMA2(acc[1][0], wp.y, x0.x, acc[1][0]);
        FFMA2(acc[0][1], wp.x, x0.y, acc[0][1]); FFMA2(acc[1][1], wp.y, x0.y, acc[1][1]);
        FFMA2(acc[0][2], wp.x, x1.x, acc[0][2]); FFMA2(acc[1][2], wp.y, x1.x, acc[1][2]);
        FFMA2(acc[0][3], wp.x, x1.y, acc[0][3]); FFMA2(acc[1][3], wp.y, x1.y, acc[1][3]);
        FFMA2(acc[0][4], wp.x, x2.x, acc[0][4]); FFMA2(acc[1][4], wp.y, x2.x, acc[1][4]);
        FFMA2(acc[0][5], wp.x, x2.y, acc[0][5]); FFMA2(acc[1][5], wp.y, x2.y, acc[1][5]);
        FFMA2(acc[0][6], wp.x, x3.x, acc[0][6]); FFMA2(acc[1][6], wp.y, x3.x, acc[1][6]);
        FFMA2(acc[0][7], wp.x, x3.y, acc[0][7]); FFMA2(acc[1][7], wp.y, x3.y, acc[1][7]);
    }

    if (tid < Dn) {           // per-chunk weight sums (pad-68 rows: conflict-free)
        float s = 0.f;
        #pragma unroll 8
        for (int t = 0; t < TC; t++) s += sm.sw[t][tid];
        g_psum[(b * NCH + ch) * Dn + tid] = s;
    }

    // acc[j][f] = (partial[d0+2j][f0+f], partial[d0+2j+1][f0+f])
    float* pp = g_partial + ((size_t)(b * NCH + ch) * Dn) * Fn;
    #pragma unroll
    for (int j = 0; j < 2; j++) {
        float lo[8], hi[8];
        #pragma unroll
        for (int f = 0; f < 8; f++) UNPACK2(lo[f], hi[f], acc[j][f]);
        float* r0 = pp + (size_t)(d0 + 2 * j) * Fn + f0;
        float* r1 = pp + (size_t)(d0 + 2 * j + 1) * Fn + f0;
        *(float4*)(r0)     = make_float4(lo[0], lo[1], lo[2], lo[3]);
        *(float4*)(r0 + 4) = make_float4(lo[4], lo[5], lo[6], lo[7]);
        *(float4*)(r1)     = make_float4(hi[0], hi[1], hi[2], hi[3]);
        *(float4*)(r1 + 4) = make_float4(hi[4], hi[5], hi[6], hi[7]);
    }
}

// ======== k4: out[b][d][f] = (sum_ch partial)/P - dic ========
// grid 512 = one block per (b,d), 128 thr, 4 groups x 8 chunks (L2-resident).
__global__ void __launch_bounds__(128) k4(const float* __restrict__ dic,
                                          float* __restrict__ out) {
    __shared__ float4 sp[4][32];
    __shared__ float sP;
    int bd = blockIdx.x;
    int b = bd >> 6, d = bd & 63;
    int tid = threadIdx.x;
    int f4 = tid & 31, grp = tid >> 5;

    if (tid < 32) {           // P = sum_ch psum
        float s = g_psum[(b * NCH + tid) * Dn + d];
        #pragma unroll
        for (int o = 16; o; o >>= 1) s += __shfl_xor_sync(0xffffffffu, s, o);
        if (tid == 0) sP = s;
    }

    const float4* p = (const float4*)g_partial
        + ((size_t)(b * NCH + grp * 8) * Dn + d) * (Fn / 4) + f4;
    float4 s = make_float4(0.f, 0.f, 0.f, 0.f);
    #pragma unroll
    for (int i = 0; i < 8; i++) {
        float4 v = p[(size_t)i * Dn * (Fn / 4)];
        s.x += v.x; s.y += v.y; s.z += v.z; s.w += v.w;
    }
    sp[grp][f4] = s;
    __syncthreads();

    if (tid < 32) {
        float4 a = sp[0][f4], b4 = sp[1][f4], c = sp[2][f4], e = sp[3][f4];
        float inv = 1.0f / sP;
        float4 dc = ((const float4*)dic)[d * (Fn / 4) + f4];
        ((float4*)out)[bd * (Fn / 4) + f4] =
            make_float4((a.x + b4.x + c.x + e.x) * inv - dc.x,
                        (a.y + b4.y + c.y + e.y) * inv - dc.y,
                        (a.z + b4.z + c.z + e.z) * inv - dc.z,
                        (a.w + b4.w + c.w + e.w) * inv - dc.w);
    }
}

// ---------------- launch ----------------
extern "C" void kernel_launch(void* const* d_in, const int* in_sizes, int n_in,
                              void* d_out, int out_size) {
    const float* x = 0; const float* dic = 0; const float* wei = 0;
    for (int i = 0; i < n_in; i++) {
        if (in_sizes[i] == Bn * Tn * Fn)      x   = (const float*)d_in[i];
        else if (in_sizes[i] == Dn * Fn)      dic = (const float*)d_in[i];
        else if (in_sizes[i] == Dn)           wei = (const float*)d_in[i];
    }
    float* out = (float*)d_out;

    int s1 = (int)sizeof(Smem1);   // ~50 KB -> 4 CTAs/SM
    int s3 = (int)sizeof(Smem3);   // ~83 KB -> 2 CTAs/SM (k3 grid is 256 CTAs)
    cudaFuncSetAttribute(k1, cudaFuncAttributeMaxDynamicSharedMemorySize, s1);
    cudaFuncSetAttribute(k3, cudaFuncAttributeMaxDynamicSharedMemorySize, s3);

    k1<<<dim3(Tn / T1, Bn), 128, s1>>>(x, dic, wei);
    k3<<<dim3(NCH, Bn), 256, s3>>>(x);
    k4<<<Bn * Dn, 128>>>(dic, out);
}